// round 3
// baseline (speedup 1.0000x reference)
#include <cuda_runtime.h>
#include <cstdint>

// Problem constants
#define BATCH 4
#define CCH   32
#define RES   64
#define PP    4
#define NWIN  4096      // 16*16*16
#define EMB   2048
#define HEADS 16
#define HD    128
#define E3    (3*EMB)

// Scratch (global device arrays; allocation-free per harness rules)
__device__ float g_tok[(size_t)BATCH * NWIN * EMB];      // 128 MB
__device__ float g_qkv[(size_t)BATCH * NWIN * E3];       // 384 MB
__device__ float g_att[(size_t)BATCH * NWIN * EMB];      // 128 MB
__device__ float g_o2 [(size_t)BATCH * NWIN * EMB];      // 128 MB

// ---------------------------------------------------------------------------
// pack: x(B,C,64,64,64) -> tok(B,N,E)
// tok[b,n,e] = x[b,c, nx*4+px, ny*4+py, nz*4+pz]
//   n = (nx*16+ny)*16+nz ; e = c*64 + px*16 + py*4 + pz
// ---------------------------------------------------------------------------
__global__ void pack_kernel(const float* __restrict__ x)
{
    size_t idx = (size_t)blockIdx.x * blockDim.x + threadIdx.x;
    const size_t total = (size_t)BATCH * NWIN * EMB;
    if (idx >= total) return;
    int e  = (int)(idx & (EMB - 1));
    size_t bn = idx >> 11;           // /2048
    int n  = (int)(bn & (NWIN - 1));
    int b  = (int)(bn >> 12);        // /4096
    int c  = e >> 6;
    int px = (e >> 4) & 3;
    int py = (e >> 2) & 3;
    int pz = e & 3;
    int nx = n >> 8;
    int ny = (n >> 4) & 15;
    int nz = n & 15;
    int X = nx * 4 + px, Y = ny * 4 + py, Z = nz * 4 + pz;
    size_t src = ((((size_t)(b * CCH + c)) * RES + X) * RES + Y) * RES + Z;
    g_tok[idx] = x[src];
}

// ---------------------------------------------------------------------------
// unpack: o3(B,N,E) -> out(B,C,64,64,64)
// out[b,c, px*16+nx, py*16+ny, pz*16+nz] = o3[b,n,e]
// ---------------------------------------------------------------------------
__global__ void unpack_kernel(const float* __restrict__ o3, float* __restrict__ out)
{
    size_t idx = (size_t)blockIdx.x * blockDim.x + threadIdx.x;
    const size_t total = (size_t)BATCH * CCH * RES * RES * RES;
    if (idx >= total) return;
    int Z = (int)(idx & 63); size_t r = idx >> 6;
    int Y = (int)(r & 63);   r >>= 6;
    int X = (int)(r & 63);   r >>= 6;
    int c = (int)(r & 31);
    int b = (int)(r >> 5);
    int px = X >> 4, nx = X & 15;
    int py = Y >> 4, ny = Y & 15;
    int pz = Z >> 4, nz = Z & 15;
    int n = (nx * 16 + ny) * 16 + nz;
    int e = c * 64 + px * 16 + py * 4 + pz;
    out[idx] = o3[((size_t)b * NWIN + n) * EMB + e];
}

// ---------------------------------------------------------------------------
// NT SGEMM: C[M,N] = A[M,K] * Bw[N,K]^T + bias[N]
// A row-major MxK, Bw row-major NxK (both K-contiguous).
// 128x128 block tile, BK=16, 256 threads, 8x8 per-thread micro-tile.
// Shared rows padded to 132 floats (528B, 16B-aligned) so float4 LDS works.
// ---------------------------------------------------------------------------
#define BM 128
#define BN 128
#define BK 16
#define TM 8
#define TN 8

__global__ __launch_bounds__(256) void gemm_nt_kernel(
    const float* __restrict__ A, const float* __restrict__ Bw,
    const float* __restrict__ bias, float* __restrict__ C,
    int M, int N, int K)
{
    __shared__ float As[BK][BM + 4];
    __shared__ float Bs[BK][BN + 4];

    const int tid = threadIdx.x;
    const int bm = blockIdx.y * BM;
    const int bn = blockIdx.x * BN;

    const int tcol = (tid & 15) * TN;
    const int trow = (tid >> 4) * TM;

    float acc[TM][TN];
    #pragma unroll
    for (int i = 0; i < TM; i++)
        #pragma unroll
        for (int j = 0; j < TN; j++) acc[i][j] = 0.f;

    for (int k0 = 0; k0 < K; k0 += BK) {
        // Load A tile (128 rows x 16 k), transpose into As[k][m]
        #pragma unroll
        for (int l = 0; l < 2; l++) {
            int f = tid + l * 256;           // 0..511 float4 slots
            int row = f >> 2;
            int c4  = (f & 3) << 2;
            float4 v = *reinterpret_cast<const float4*>(
                &A[(size_t)(bm + row) * K + k0 + c4]);
            As[c4 + 0][row] = v.x;
            As[c4 + 1][row] = v.y;
            As[c4 + 2][row] = v.z;
            As[c4 + 3][row] = v.w;
        }
        // Load B tile (128 rows x 16 k), transpose into Bs[k][n]
        #pragma unroll
        for (int l = 0; l < 2; l++) {
            int f = tid + l * 256;
            int row = f >> 2;
            int c4  = (f & 3) << 2;
            float4 v = *reinterpret_cast<const float4*>(
                &Bw[(size_t)(bn + row) * K + k0 + c4]);
            Bs[c4 + 0][row] = v.x;
            Bs[c4 + 1][row] = v.y;
            Bs[c4 + 2][row] = v.z;
            Bs[c4 + 3][row] = v.w;
        }
        __syncthreads();

        #pragma unroll
        for (int k = 0; k < BK; k++) {
            float ar[TM], br[TN];
            // vectorized LDS (addresses 16B-aligned: trow/tcol multiples of 8)
            *reinterpret_cast<float4*>(&ar[0]) =
                *reinterpret_cast<const float4*>(&As[k][trow]);
            *reinterpret_cast<float4*>(&ar[4]) =
                *reinterpret_cast<const float4*>(&As[k][trow + 4]);
            *reinterpret_cast<float4*>(&br[0]) =
                *reinterpret_cast<const float4*>(&Bs[k][tcol]);
            *reinterpret_cast<float4*>(&br[4]) =
                *reinterpret_cast<const float4*>(&Bs[k][tcol + 4]);
            #pragma unroll
            for (int i = 0; i < TM; i++)
                #pragma unroll
                for (int j = 0; j < TN; j++)
                    acc[i][j] += ar[i] * br[j];
        }
        __syncthreads();
    }

    #pragma unroll
    for (int i = 0; i < TM; i++) {
        #pragma unroll
        for (int j = 0; j < TN; j++) {
            C[(size_t)(bm + trow + i) * N + bn + tcol + j] =
                acc[i][j] + bias[bn + tcol + j];
        }
    }
}

// ---------------------------------------------------------------------------
// attention: seq = B = 4, batch = N*H. One warp per (n,h).
// ---------------------------------------------------------------------------
__global__ void attn_kernel(const float* __restrict__ qkv, float* __restrict__ o)
{
    int warp = (int)((blockIdx.x * (size_t)blockDim.x + threadIdx.x) >> 5);
    int lane = threadIdx.x & 31;
    if (warp >= NWIN * HEADS) return;
    int n = warp >> 4;
    int h = warp & 15;

    float q[4][4], k[4][4], v[4][4];
    #pragma unroll
    for (int s = 0; s < 4; s++) {
        const float* base = qkv + (size_t)s * NWIN * E3 + (size_t)n * E3 + h * HD;
        #pragma unroll
        for (int i = 0; i < 4; i++) {
            int d = lane + 32 * i;
            q[s][i] = base[d];
            k[s][i] = base[EMB + d];
            v[s][i] = base[2 * EMB + d];
        }
    }

    const float scale = 0.08838834764831845f;   // 1/sqrt(128)
    float sc[4][4];
    #pragma unroll
    for (int s = 0; s < 4; s++) {
        #pragma unroll
        for (int t = 0; t < 4; t++) {
            float p = 0.f;
            #pragma unroll
            for (int i = 0; i < 4; i++) p += q[s][i] * k[t][i];
            #pragma unroll
            for (int off = 16; off; off >>= 1)
                p += __shfl_xor_sync(0xFFFFFFFFu, p, off);
            sc[s][t] = p * scale;
        }
    }

    #pragma unroll
    for (int s = 0; s < 4; s++) {
        float m = fmaxf(fmaxf(sc[s][0], sc[s][1]), fmaxf(sc[s][2], sc[s][3]));
        float e[4], sum = 0.f;
        #pragma unroll
        for (int t = 0; t < 4; t++) { e[t] = __expf(sc[s][t] - m); sum += e[t]; }
        float inv = 1.f / sum;
        float* ob = o + (size_t)s * NWIN * EMB + (size_t)n * EMB + h * HD;
        #pragma unroll
        for (int i = 0; i < 4; i++) {
            float accv = 0.f;
            #pragma unroll
            for (int t = 0; t < 4; t++) accv += e[t] * v[t][i];
            ob[lane + 32 * i] = accv * inv;
        }
    }
}

// ---------------------------------------------------------------------------
extern "C" void kernel_launch(void* const* d_in, const int* in_sizes, int n_in,
                              void* d_out, int out_size)
{
    const float* x     = (const float*)d_in[0];
    const float* w_in  = (const float*)d_in[1];
    const float* b_in  = (const float*)d_in[2];
    const float* w_out = (const float*)d_in[3];
    const float* b_out = (const float*)d_in[4];
    const float* w_mlp = (const float*)d_in[5];
    const float* b_mlp = (const float*)d_in[6];
    float* out = (float*)d_out;

    float *tok, *qkv, *att, *o2;
    cudaGetSymbolAddress((void**)&tok, g_tok);
    cudaGetSymbolAddress((void**)&qkv, g_qkv);
    cudaGetSymbolAddress((void**)&att, g_att);
    cudaGetSymbolAddress((void**)&o2,  g_o2);

    const size_t tok_elems = (size_t)BATCH * NWIN * EMB;   // 33554432

    // 1) pack
    pack_kernel<<<(unsigned)((tok_elems + 255) / 256), 256>>>(x);

    // 2) qkv = tok @ w_in^T + b_in   : M=16384, N=6144, K=2048
    {
        dim3 grid(E3 / BN, (BATCH * NWIN) / BM);
        gemm_nt_kernel<<<grid, 256>>>(tok, w_in, b_in, qkv,
                                      BATCH * NWIN, E3, EMB);
    }

    // 3) attention (warp per (n,h))
    {
        int warps = NWIN * HEADS;                 // 65536
        int threads = 256;
        int blocks = warps * 32 / threads;        // 8192
        attn_kernel<<<blocks, threads>>>(qkv, att);
    }

    // 4) o2 = att @ w_out^T + b_out : M=16384, N=2048, K=2048
    {
        dim3 grid(EMB / BN, (BATCH * NWIN) / BM);
        gemm_nt_kernel<<<grid, 256>>>(att, w_out, b_out, o2,
                                      BATCH * NWIN, EMB, EMB);
    }

    // 5) o3 = o2 @ w_mlp^T + b_mlp  (write into g_tok, no longer needed)
    {
        dim3 grid(EMB / BN, (BATCH * NWIN) / BM);
        gemm_nt_kernel<<<grid, 256>>>(o2, w_mlp, b_mlp, tok,
                                      BATCH * NWIN, EMB, EMB);
    }

    // 6) unpack
    unpack_kernel<<<(unsigned)((tok_elems + 255) / 256), 256>>>(tok, out);
}

// round 6
// speedup vs baseline: 2.1938x; 2.1938x over previous
#include <cuda_runtime.h>
#include <cuda_bf16.h>
#include <cstdint>

// ---------------------------------------------------------------------------
// Problem constants
// ---------------------------------------------------------------------------
#define BATCH 4
#define CCH   32
#define RES   64
#define NWIN  4096      // 16*16*16
#define EMB   2048
#define HEADS 16
#define HD    128
#define E3    (3*EMB)
#define MTOT  (BATCH*NWIN)   // 16384
#define KDIM  2048

// GEMM tiling (mma.sync path, arch-neutral)
#define BM 128
#define BN 128
#define BK 64                        // bf16 elems: 128 bytes per row
#define NSTAGE 3
#define A_STAGE_B (BM*128)           // 16 KB
#define B_STAGE_B (BN*128)           // 16 KB
#define STAGE_B   (A_STAGE_B + B_STAGE_B)     // 32 KB
#define GEMM_SMEM (NSTAGE*STAGE_B)            // 96 KB
#define NC 96                        // 3 segments * (2048/64)

// ---------------------------------------------------------------------------
// Scratch
// ---------------------------------------------------------------------------
__device__ __nv_bfloat16 g_ah[(size_t)MTOT * KDIM];
__device__ __nv_bfloat16 g_al[(size_t)MTOT * KDIM];
__device__ float g_f1[(size_t)MTOT * E3];
__device__ float g_f2[(size_t)MTOT * EMB];
__device__ __nv_bfloat16 g_wih[(size_t)E3 * KDIM];
__device__ __nv_bfloat16 g_wil[(size_t)E3 * KDIM];
__device__ __nv_bfloat16 g_woh[(size_t)EMB * KDIM];
__device__ __nv_bfloat16 g_wol[(size_t)EMB * KDIM];
__device__ __nv_bfloat16 g_wmh[(size_t)EMB * KDIM];
__device__ __nv_bfloat16 g_wml[(size_t)EMB * KDIM];

// ---------------------------------------------------------------------------
// helpers
// ---------------------------------------------------------------------------
__device__ __forceinline__ uint32_t smem_u32(const void* p) {
    uint32_t a;
    asm("{ .reg .u64 t; cvta.to.shared.u64 t, %1; cvt.u32.u64 %0, t; }"
        : "=r"(a) : "l"(p));
    return a;
}
__device__ __forceinline__ uint32_t swz(uint32_t off) {
    return off ^ ((off >> 3) & 0x70);
}
__device__ __forceinline__ void ldsm_x4(uint32_t a, uint32_t& r0, uint32_t& r1,
                                        uint32_t& r2, uint32_t& r3) {
    asm volatile("ldmatrix.sync.aligned.m8n8.x4.shared.b16 {%0,%1,%2,%3}, [%4];"
                 : "=r"(r0), "=r"(r1), "=r"(r2), "=r"(r3) : "r"(a));
}
__device__ __forceinline__ void mma_bf16(float& d0, float& d1, float& d2, float& d3,
                                         uint32_t a0, uint32_t a1, uint32_t a2, uint32_t a3,
                                         uint32_t b0, uint32_t b1) {
    asm volatile(
        "mma.sync.aligned.m16n8k16.row.col.f32.bf16.bf16.f32 "
        "{%0,%1,%2,%3}, {%4,%5,%6,%7}, {%8,%9}, {%0,%1,%2,%3};"
        : "+f"(d0), "+f"(d1), "+f"(d2), "+f"(d3)
        : "r"(a0), "r"(a1), "r"(a2), "r"(a3), "r"(b0), "r"(b1));
}

// ---------------------------------------------------------------------------
// pack + split
// ---------------------------------------------------------------------------
__global__ void pack_split_kernel(const float* __restrict__ x)
{
    size_t idx = (size_t)blockIdx.x * blockDim.x + threadIdx.x;
    const size_t total = (size_t)MTOT * EMB;
    if (idx >= total) return;
    int e  = (int)(idx & (EMB - 1));
    size_t bn = idx >> 11;
    int n  = (int)(bn & (NWIN - 1));
    int b  = (int)(bn >> 12);
    int c  = e >> 6;
    int px = (e >> 4) & 3;
    int py = (e >> 2) & 3;
    int pz = e & 3;
    int nx = n >> 8;
    int ny = (n >> 4) & 15;
    int nz = n & 15;
    int X = nx * 4 + px, Y = ny * 4 + py, Z = nz * 4 + pz;
    size_t src = ((((size_t)(b * CCH + c)) * RES + X) * RES + Y) * RES + Z;
    float v = x[src];
    __nv_bfloat16 hi = __float2bfloat16(v);
    g_ah[idx] = hi;
    g_al[idx] = __float2bfloat16(v - __bfloat162float(hi));
}

__global__ void split_kernel(const float* __restrict__ s,
                             __nv_bfloat16* __restrict__ h,
                             __nv_bfloat16* __restrict__ l, size_t n)
{
    size_t i = (size_t)blockIdx.x * blockDim.x + threadIdx.x;
    if (i >= n) return;
    float v = s[i];
    __nv_bfloat16 hi = __float2bfloat16(v);
    h[i] = hi;
    l[i] = __float2bfloat16(v - __bfloat162float(hi));
}

__global__ void unpack_kernel(const float* __restrict__ o3, float* __restrict__ out)
{
    size_t idx = (size_t)blockIdx.x * blockDim.x + threadIdx.x;
    const size_t total = (size_t)BATCH * CCH * RES * RES * RES;
    if (idx >= total) return;
    int Z = (int)(idx & 63); size_t r = idx >> 6;
    int Y = (int)(r & 63);   r >>= 6;
    int X = (int)(r & 63);   r >>= 6;
    int c = (int)(r & 31);
    int b = (int)(r >> 5);
    int px = X >> 4, nx = X & 15;
    int py = Y >> 4, ny = Y & 15;
    int pz = Z >> 4, nz = Z & 15;
    int n = (nx * 16 + ny) * 16 + nz;
    int e = c * 64 + px * 16 + py * 4 + pz;
    out[idx] = o3[((size_t)b * NWIN + n) * EMB + e];
}

// ---------------------------------------------------------------------------
// bf16x3-split HMMA GEMM: C[M,N] = A[M,K]*Bw[N,K]^T + bias (fp32)
// ---------------------------------------------------------------------------
__device__ __forceinline__ void load_chunk(
    int c, int slot, uint32_t sb, int bm, int bn, int tid,
    const __nv_bfloat16* __restrict__ a_hi, const __nv_bfloat16* __restrict__ a_lo,
    const __nv_bfloat16* __restrict__ b_hi, const __nv_bfloat16* __restrict__ b_lo)
{
    int seg = c >> 5;
    int kc  = (c & 31) << 6;
    const __nv_bfloat16* ap = (seg == 1) ? a_lo : a_hi;
    const __nv_bfloat16* bp = (seg == 2) ? b_lo : b_hi;
    uint32_t base = sb + slot * STAGE_B;
    #pragma unroll
    for (int j = 0; j < 8; j++) {
        int o = tid + (j << 8);                 // 0..2047
        bool isA = o < 1024;
        int oo = o & 1023;
        int row = oo >> 3, c16 = oo & 7;
        const __nv_bfloat16* src = isA
            ? ap + ((size_t)(bm + row) * KDIM + kc + (c16 << 3))
            : bp + ((size_t)(bn + row) * KDIM + kc + (c16 << 3));
        uint32_t off = (uint32_t)((row << 7) + (c16 << 4));
        uint32_t dst = base + (isA ? 0u : (uint32_t)A_STAGE_B) + swz(off);
        asm volatile("cp.async.cg.shared.global [%0], [%1], 16;"
                     :: "r"(dst), "l"(src));
    }
}

__global__ __launch_bounds__(256) void gemm_mma_kernel(
    const __nv_bfloat16* __restrict__ a_hi, const __nv_bfloat16* __restrict__ a_lo,
    const __nv_bfloat16* __restrict__ b_hi, const __nv_bfloat16* __restrict__ b_lo,
    const float* __restrict__ bias, float* __restrict__ C, int Ncols)
{
    extern __shared__ char smem[];
    const uint32_t sb = smem_u32(smem);
    const int tid  = threadIdx.x;
    const int wid  = tid >> 5;
    const int lane = tid & 31;
    const int bm = blockIdx.y * BM;
    const int bn = blockIdx.x * BN;
    const int wm = (wid >> 2) * 64;      // warp row offset  (2 warps in M)
    const int wn = (wid & 3) * 32;       // warp col offset  (4 warps in N)

    float acc[4][4][4];
    #pragma unroll
    for (int i = 0; i < 4; i++)
        #pragma unroll
        for (int j = 0; j < 4; j++)
            #pragma unroll
            for (int q = 0; q < 4; q++) acc[i][j][q] = 0.f;

    // ldmatrix per-lane address components (logical offsets, swizzled later)
    const int lrow = lane & 15;          // row within 16-row tile
    const int lcol = (lane >> 4) << 4;   // 0 or 16 bytes (k half)

    // prologue
    load_chunk(0, 0, sb, bm, bn, tid, a_hi, a_lo, b_hi, b_lo);
    asm volatile("cp.async.commit_group;" ::: "memory");
    load_chunk(1, 1, sb, bm, bn, tid, a_hi, a_lo, b_hi, b_lo);
    asm volatile("cp.async.commit_group;" ::: "memory");

    for (int c = 0; c < NC; c++) {
        asm volatile("cp.async.wait_group 1;" ::: "memory");
        __syncthreads();

        int cn = c + 2;
        if (cn < NC)
            load_chunk(cn, cn % NSTAGE, sb, bm, bn, tid, a_hi, a_lo, b_hi, b_lo);
        asm volatile("cp.async.commit_group;" ::: "memory");

        uint32_t abase = sb + (c % NSTAGE) * STAGE_B;
        uint32_t bbase = abase + A_STAGE_B;

        #pragma unroll
        for (int ks = 0; ks < 4; ks++) {
            const int kb = ks * 32 + lcol;         // byte offset in 128B row
            uint32_t a[4][4];
            #pragma unroll
            for (int mt = 0; mt < 4; mt++) {
                uint32_t off = (uint32_t)((wm + mt * 16 + lrow) << 7) + kb;
                ldsm_x4(abase + swz(off), a[mt][0], a[mt][1], a[mt][2], a[mt][3]);
            }
            uint32_t b[4][2];
            #pragma unroll
            for (int p = 0; p < 2; p++) {
                uint32_t off = (uint32_t)((wn + p * 16 + lrow) << 7) + kb;
                uint32_t r0, r1, r2, r3;
                ldsm_x4(bbase + swz(off), r0, r1, r2, r3);
                b[2 * p][0] = r0; b[2 * p][1] = r2;       // n tile p*16..p*16+7
                b[2 * p + 1][0] = r1; b[2 * p + 1][1] = r3; // n tile +8..+15
            }
            #pragma unroll
            for (int mt = 0; mt < 4; mt++)
                #pragma unroll
                for (int nt = 0; nt < 4; nt++)
                    mma_bf16(acc[mt][nt][0], acc[mt][nt][1],
                             acc[mt][nt][2], acc[mt][nt][3],
                             a[mt][0], a[mt][1], a[mt][2], a[mt][3],
                             b[nt][0], b[nt][1]);
        }
        __syncthreads();
    }

    // epilogue: d-fragment mapping: rows (lane>>2), (lane>>2)+8; cols 2*(lane&3)
    const int er = lane >> 2;
    const int ec = (lane & 3) * 2;
    #pragma unroll
    for (int mt = 0; mt < 4; mt++) {
        int row0 = bm + wm + mt * 16 + er;
        #pragma unroll
        for (int nt = 0; nt < 4; nt++) {
            int col = bn + wn + nt * 8 + ec;
            float b0 = bias[col], b1 = bias[col + 1];
            float2 v0 = make_float2(acc[mt][nt][0] + b0, acc[mt][nt][1] + b1);
            float2 v1 = make_float2(acc[mt][nt][2] + b0, acc[mt][nt][3] + b1);
            *reinterpret_cast<float2*>(C + (size_t)row0 * Ncols + col) = v0;
            *reinterpret_cast<float2*>(C + (size_t)(row0 + 8) * Ncols + col) = v1;
        }
    }
}

// ---------------------------------------------------------------------------
// attention: seq = B = 4, batch = N*H. One warp per (n,h).
// ---------------------------------------------------------------------------
__global__ void attn_kernel(const float* __restrict__ qkv, float* __restrict__ o)
{
    int warp = (int)((blockIdx.x * (size_t)blockDim.x + threadIdx.x) >> 5);
    int lane = threadIdx.x & 31;
    if (warp >= NWIN * HEADS) return;
    int n = warp >> 4;
    int h = warp & 15;

    float q[4][4], k[4][4], v[4][4];
    #pragma unroll
    for (int s = 0; s < 4; s++) {
        const float* base = qkv + (size_t)s * NWIN * E3 + (size_t)n * E3 + h * HD;
        #pragma unroll
        for (int i = 0; i < 4; i++) {
            int d = lane + 32 * i;
            q[s][i] = base[d];
            k[s][i] = base[EMB + d];
            v[s][i] = base[2 * EMB + d];
        }
    }

    const float scale = 0.08838834764831845f;
    float sc[4][4];
    #pragma unroll
    for (int s = 0; s < 4; s++) {
        #pragma unroll
        for (int t = 0; t < 4; t++) {
            float p = 0.f;
            #pragma unroll
            for (int i = 0; i < 4; i++) p += q[s][i] * k[t][i];
            #pragma unroll
            for (int off = 16; off; off >>= 1)
                p += __shfl_xor_sync(0xFFFFFFFFu, p, off);
            sc[s][t] = p * scale;
        }
    }

    #pragma unroll
    for (int s = 0; s < 4; s++) {
        float m = fmaxf(fmaxf(sc[s][0], sc[s][1]), fmaxf(sc[s][2], sc[s][3]));
        float e[4], sum = 0.f;
        #pragma unroll
        for (int t = 0; t < 4; t++) { e[t] = __expf(sc[s][t] - m); sum += e[t]; }
        float inv = 1.f / sum;
        float* ob = o + (size_t)s * NWIN * EMB + (size_t)n * EMB + h * HD;
        #pragma unroll
        for (int i = 0; i < 4; i++) {
            float accv = 0.f;
            #pragma unroll
            for (int t = 0; t < 4; t++) accv += e[t] * v[t][i];
            ob[lane + 32 * i] = accv * inv;
        }
    }
}

// ---------------------------------------------------------------------------
extern "C" void kernel_launch(void* const* d_in, const int* in_sizes, int n_in,
                              void* d_out, int out_size)
{
    const float* x     = (const float*)d_in[0];
    const float* w_in  = (const float*)d_in[1];
    const float* b_in  = (const float*)d_in[2];
    const float* w_out = (const float*)d_in[3];
    const float* b_out = (const float*)d_in[4];
    const float* w_mlp = (const float*)d_in[5];
    const float* b_mlp = (const float*)d_in[6];
    float* out = (float*)d_out;

    __nv_bfloat16 *ah, *al, *wih, *wil, *woh, *wol, *wmh, *wml;
    float *f1, *f2;
    cudaGetSymbolAddress((void**)&ah,  g_ah);
    cudaGetSymbolAddress((void**)&al,  g_al);
    cudaGetSymbolAddress((void**)&f1,  g_f1);
    cudaGetSymbolAddress((void**)&f2,  g_f2);
    cudaGetSymbolAddress((void**)&wih, g_wih);
    cudaGetSymbolAddress((void**)&wil, g_wil);
    cudaGetSymbolAddress((void**)&woh, g_woh);
    cudaGetSymbolAddress((void**)&wol, g_wol);
    cudaGetSymbolAddress((void**)&wmh, g_wmh);
    cudaGetSymbolAddress((void**)&wml, g_wml);

    cudaFuncSetAttribute(gemm_mma_kernel,
                         cudaFuncAttributeMaxDynamicSharedMemorySize, GEMM_SMEM);

    const size_t act_elems = (size_t)MTOT * EMB;
    const size_t win_elems = (size_t)E3 * KDIM;
    const size_t w2_elems  = (size_t)EMB * KDIM;

    split_kernel<<<(unsigned)((win_elems + 255) / 256), 256>>>(w_in,  wih, wil, win_elems);
    split_kernel<<<(unsigned)((w2_elems  + 255) / 256), 256>>>(w_out, woh, wol, w2_elems);
    split_kernel<<<(unsigned)((w2_elems  + 255) / 256), 256>>>(w_mlp, wmh, wml, w2_elems);

    pack_split_kernel<<<(unsigned)((act_elems + 255) / 256), 256>>>(x);

    // GEMM1: qkv = tok @ w_in^T + b_in   (N = 6144)
    {
        dim3 grid(E3 / BN, MTOT / BM);       // (48, 128)
        gemm_mma_kernel<<<grid, 256, GEMM_SMEM>>>(ah, al, wih, wil, b_in, f1, E3);
    }

    attn_kernel<<<NWIN * HEADS * 32 / 256, 256>>>(f1, f2);

    split_kernel<<<(unsigned)((act_elems + 255) / 256), 256>>>(f2, ah, al, act_elems);

    // GEMM2
    {
        dim3 grid(EMB / BN, MTOT / BM);      // (16, 128)
        gemm_mma_kernel<<<grid, 256, GEMM_SMEM>>>(ah, al, woh, wol, b_out, f2, EMB);
    }

    split_kernel<<<(unsigned)((act_elems + 255) / 256), 256>>>(f2, ah, al, act_elems);

    // GEMM3
    {
        dim3 grid(EMB / BN, MTOT / BM);
        gemm_mma_kernel<<<grid, 256, GEMM_SMEM>>>(ah, al, wmh, wml, b_mlp, f2, EMB);
    }

    unpack_kernel<<<(unsigned)((act_elems + 255) / 256), 256>>>(f2, out);
}